// round 9
// baseline (speedup 1.0000x reference)
#include <cuda_runtime.h>
#include <cuda_bf16.h>
#include <cstdint>

#define G     128
#define NN    512
#define D     256
#define BT    128
#define KTOT  512              // bf16 per row in g_zs: [hi(256) | lo(256)]
#define ROWB  (KTOT * 2)       // 1024 bytes per row
#define KC    32               // K elements per chunk
#define NCH   (D / KC)         // 8 chunks
#define NTOT  (G * NN)

// Scratch: split z into bf16 hi|lo (64 MB)
__device__ __nv_bfloat16 g_zs[(size_t)NTOT * KTOT];

__constant__ int c_bi[10] = {0,0,0,0,1,1,1,2,2,3};
__constant__ int c_bj[10] = {0,1,2,3,1,2,3,2,3,3};

#define SWZ64(o) ((o) ^ (((o) >> 3) & 0x30))

__device__ __forceinline__ uint32_t smem_u32(const void* p) {
    uint32_t a;
    asm("{ .reg .u64 t; cvta.to.shared.u64 t, %1; cvt.u32.u64 %0, t; }" : "=r"(a) : "l"(p));
    return a;
}

#define CP_ASYNC16(dst, src) \
    asm volatile("cp.async.ca.shared.global [%0], [%1], 16;" :: "r"(dst), "l"(src))
#define CP_COMMIT()  asm volatile("cp.async.commit_group;" ::: "memory")
#define CP_WAIT0()   asm volatile("cp.async.wait_group 0;" ::: "memory")
#define CP_WAIT1()   asm volatile("cp.async.wait_group 1;" ::: "memory")

#define LDMX4(r0, r1, r2, r3, addr) \
    asm volatile("ldmatrix.sync.aligned.m8n8.x4.shared.b16 {%0,%1,%2,%3}, [%4];" \
                 : "=r"(r0), "=r"(r1), "=r"(r2), "=r"(r3) : "r"(addr))

#define MMA16816(d0, d1, d2, d3, a0, a1, a2, a3, b0, b1) \
    asm volatile("mma.sync.aligned.m16n8k16.row.col.f32.bf16.bf16.f32 " \
                 "{%0,%1,%2,%3}, {%4,%5,%6,%7}, {%8,%9}, {%0,%1,%2,%3};" \
                 : "+f"(d0), "+f"(d1), "+f"(d2), "+f"(d3) \
                 : "r"(a0), "r"(a1), "r"(a2), "r"(a3), "r"(b0), "r"(b1))

// SMEM: 3 stages x 4 buffers (A_hi, A_lo, B_hi, B_lo) x 8KB = 96 KB pipeline.
// Epilogue reuses as float tile [128][132] = 67,584 B.
#define BUFSZ      8192
#define STAGE_SZ   (4 * BUFSZ)          // 32768
#define NSTAGE     3
#define EPAD       132
#define SMEM_BYTES (NSTAGE * STAGE_SZ)  // 98304 >= 67584

// ---------------- Phase 1: split z -> bf16 hi|lo ----------------
__global__ void split_kernel(const float* __restrict__ z) {
    size_t i = ((size_t)blockIdx.x * blockDim.x + threadIdx.x) * 4;
    if (i >= (size_t)NTOT * D) return;
    float4 v = *reinterpret_cast<const float4*>(z + i);
    float f[4] = {v.x, v.y, v.z, v.w};
    union { unsigned short s[4]; uint2 u; } hi, lo;
    #pragma unroll
    for (int k = 0; k < 4; ++k) {
        __nv_bfloat16 h = __float2bfloat16(f[k]);
        hi.s[k] = __bfloat16_as_ushort(h);
        __nv_bfloat16 l = __float2bfloat16(f[k] - __bfloat162float(h));
        lo.s[k] = __bfloat16_as_ushort(l);
    }
    size_t node = i >> 8;
    size_t kk   = i & 255;
    __nv_bfloat16* row = g_zs + node * KTOT;
    *reinterpret_cast<uint2*>(row + kk)       = hi.u;
    *reinterpret_cast<uint2*>(row + 256 + kk) = lo.u;
}

// ---------------- Phase 2: HMMA GEMM (3-term split) + sigmoid ----------------
__global__ __launch_bounds__(256, 2)
void decoder_hmma_kernel(float* __restrict__ out) {
    extern __shared__ __align__(1024) char smem[];
    const uint32_t sbase = smem_u32(smem);
    float* smemF = reinterpret_cast<float*>(smem);

    const int tid = threadIdx.x;
    const int w   = tid >> 5;
    const int l   = tid & 31;
    const int wm  = w & 3;          // 0..3: 32-row block
    const int wn  = w >> 2;         // 0..1: 64-col block

    const int bx   = blockIdx.x;
    const int g    = bx / 10;
    const int pair = bx - g * 10;
    const int bi   = c_bi[pair];
    const int bj   = c_bj[pair];
    const bool diag = (bi == bj);

    const char* gA = reinterpret_cast<const char*>(g_zs) + ((size_t)g * NN + (size_t)bi * BT) * ROWB;
    const char* gB = reinterpret_cast<const char*>(g_zs) + ((size_t)g * NN + (size_t)bj * BT) * ROWB;

    // Per chunk c (32 elems = 64B): hi half at byte c*64, lo half at 512 + c*64.
    auto prefetch = [&](int c, int stage) {
        const uint32_t st = sbase + stage * STAGE_SZ;
        const int nbuf = diag ? 2 : 4;
        #pragma unroll
        for (int which = 0; which < 4; ++which) {
            if (which >= nbuf) break;
            const char* gp   = (which < 2) ? gA : gB;
            const int   hoff = (which & 1) ? 512 : 0;
            const uint32_t dst0 = st + which * BUFSZ;
            #pragma unroll
            for (int it = 0; it < 2; ++it) {
                int f   = it * 256 + tid;     // 0..511
                int row = f >> 2;
                int q   = f & 3;
                const char* src = gp + (size_t)row * ROWB + hoff + c * 64 + q * 16;
                CP_ASYNC16(dst0 + SWZ64((uint32_t)(row * 64 + q * 16)), src);
            }
        }
        CP_COMMIT();
    };

    float acc[2][8][4];
    #pragma unroll
    for (int mi = 0; mi < 2; ++mi)
        #pragma unroll
        for (int ni = 0; ni < 8; ++ni)
            #pragma unroll
            for (int r = 0; r < 4; ++r) acc[mi][ni][r] = 0.0f;

    // ldmatrix lane-derived constants
    const int mat = l >> 3;
    const int lr  = l & 7;
    const int a_roff = (mat & 1) * 8 + lr;
    const int a_koff = (mat >> 1) * 16;
    const int b_roff = (mat >> 1) * 8 + lr;
    const int b_koff = (mat & 1) * 16;

    prefetch(0, 0);
    prefetch(1, 1);

    for (int c = 0; c < NCH; ++c) {
        // Ensure chunk c's cp.async group has landed (<=1 pending keeps c+1 in flight)
        if (c >= NCH - 2) { CP_WAIT0(); } else { CP_WAIT1(); }
        __syncthreads();
        if (c + 2 < NCH) prefetch(c + 2, (c + 2) % NSTAGE);

        const uint32_t st = sbase + (c % NSTAGE) * STAGE_SZ;
        const uint32_t A_hi = st;
        const uint32_t A_lo = st + BUFSZ;
        const uint32_t B_hi = diag ? A_hi : (st + 2 * BUFSZ);
        const uint32_t B_lo = diag ? A_lo : (st + 3 * BUFSZ);

        // Register-hoisted 3-term schedule per k16 step:
        //   ld A_hi, B_hi -> term0 ; ld B_lo -> term1 (reuse A_hi) ; ld A_lo -> term2 (reuse B_hi)
        #pragma unroll
        for (int ks = 0; ks < 2; ++ks) {
            const int kb = ks * 32;

            uint32_t ah[2][4];
            #pragma unroll
            for (int mi = 0; mi < 2; ++mi) {
                int row = wm * 32 + mi * 16 + a_roff;
                LDMX4(ah[mi][0], ah[mi][1], ah[mi][2], ah[mi][3],
                      A_hi + SWZ64((uint32_t)(row * 64 + kb + a_koff)));
            }
            uint32_t bh[8][2];
            #pragma unroll
            for (int np = 0; np < 4; ++np) {
                int row = wn * 64 + np * 16 + b_roff;
                LDMX4(bh[np*2][0], bh[np*2][1], bh[np*2+1][0], bh[np*2+1][1],
                      B_hi + SWZ64((uint32_t)(row * 64 + kb + b_koff)));
            }
            #pragma unroll
            for (int mi = 0; mi < 2; ++mi)
                #pragma unroll
                for (int ni = 0; ni < 8; ++ni)
                    MMA16816(acc[mi][ni][0], acc[mi][ni][1], acc[mi][ni][2], acc[mi][ni][3],
                             ah[mi][0], ah[mi][1], ah[mi][2], ah[mi][3],
                             bh[ni][0], bh[ni][1]);

            uint32_t bl[8][2];
            #pragma unroll
            for (int np = 0; np < 4; ++np) {
                int row = wn * 64 + np * 16 + b_roff;
                LDMX4(bl[np*2][0], bl[np*2][1], bl[np*2+1][0], bl[np*2+1][1],
                      B_lo + SWZ64((uint32_t)(row * 64 + kb + b_koff)));
            }
            #pragma unroll
            for (int mi = 0; mi < 2; ++mi)
                #pragma unroll
                for (int ni = 0; ni < 8; ++ni)
                    MMA16816(acc[mi][ni][0], acc[mi][ni][1], acc[mi][ni][2], acc[mi][ni][3],
                             ah[mi][0], ah[mi][1], ah[mi][2], ah[mi][3],
                             bl[ni][0], bl[ni][1]);

            uint32_t al[2][4];
            #pragma unroll
            for (int mi = 0; mi < 2; ++mi) {
                int row = wm * 32 + mi * 16 + a_roff;
                LDMX4(al[mi][0], al[mi][1], al[mi][2], al[mi][3],
                      A_lo + SWZ64((uint32_t)(row * 64 + kb + a_koff)));
            }
            #pragma unroll
            for (int mi = 0; mi < 2; ++mi)
                #pragma unroll
                for (int ni = 0; ni < 8; ++ni)
                    MMA16816(acc[mi][ni][0], acc[mi][ni][1], acc[mi][ni][2], acc[mi][ni][3],
                             al[mi][0], al[mi][1], al[mi][2], al[mi][3],
                             bh[ni][0], bh[ni][1]);
        }
    }

    // ---- Epilogue: sigmoid -> smem tile -> coalesced stores (+ mirror) ----
    __syncthreads();   // all warps done reading pipeline smem before tile reuse

    const int tq  = l >> 2;
    const int tc2 = (l & 3) * 2;
    #pragma unroll
    for (int mi = 0; mi < 2; ++mi) {
        #pragma unroll
        for (int ni = 0; ni < 8; ++ni) {
            int rr = wm * 32 + mi * 16 + tq;
            int cc = wn * 64 + ni * 8 + tc2;
            float2 v0, v1;
            v0.x = __fdividef(1.0f, 1.0f + __expf(-acc[mi][ni][0]));
            v0.y = __fdividef(1.0f, 1.0f + __expf(-acc[mi][ni][1]));
            v1.x = __fdividef(1.0f, 1.0f + __expf(-acc[mi][ni][2]));
            v1.y = __fdividef(1.0f, 1.0f + __expf(-acc[mi][ni][3]));
            *reinterpret_cast<float2*>(&smemF[rr * EPAD + cc])       = v0;
            *reinterpret_cast<float2*>(&smemF[(rr + 8) * EPAD + cc]) = v1;
        }
    }
    __syncthreads();

    float* outg = out + (size_t)g * NN * NN;
    const int rbase = bi * BT;
    const int cbase = bj * BT;

    #pragma unroll
    for (int t4 = tid; t4 < BT * 32; t4 += 256) {
        int row = t4 >> 5, q = t4 & 31;
        float4 v = *reinterpret_cast<const float4*>(&smemF[row * EPAD + q * 4]);
        *reinterpret_cast<float4*>(&outg[(size_t)(rbase + row) * NN + cbase + q * 4]) = v;
    }
    if (!diag) {
        #pragma unroll
        for (int t4 = tid; t4 < BT * 32; t4 += 256) {
            int tcc = t4 >> 5, q = t4 & 31;
            float4 v;
            v.x = smemF[(q * 4 + 0) * EPAD + tcc];
            v.y = smemF[(q * 4 + 1) * EPAD + tcc];
            v.z = smemF[(q * 4 + 2) * EPAD + tcc];
            v.w = smemF[(q * 4 + 3) * EPAD + tcc];
            *reinterpret_cast<float4*>(&outg[(size_t)(cbase + tcc) * NN + rbase + q * 4]) = v;
        }
    }
}

extern "C" void kernel_launch(void* const* d_in, const int* in_sizes, int n_in,
                              void* d_out, int out_size) {
    const float* z = (const float*)d_in[0];
    float* out = (float*)d_out;

    cudaFuncSetAttribute(decoder_hmma_kernel, cudaFuncAttributeMaxDynamicSharedMemorySize, SMEM_BYTES);

    size_t nvec = ((size_t)NTOT * D) / 4;
    split_kernel<<<(int)((nvec + 255) / 256), 256>>>(z);
    decoder_hmma_kernel<<<G * 10, 256, SMEM_BYTES>>>(out);
}

// round 11
// speedup vs baseline: 1.6395x; 1.6395x over previous
#include <cuda_runtime.h>
#include <cuda_fp16.h>
#include <cstdint>

#define G     128
#define NN    512
#define D     256
#define BT    128
#define ROWB  (D * 2)          // 512 bytes per fp16 row
#define KC    64               // K elems per chunk = 128 bytes
#define NCH   (D / KC)         // 4 chunks
#define NTOT  (G * NN)

// Scratch: z converted to fp16 (32 MB)
__device__ __half g_zh[(size_t)NTOT * D];

__constant__ int c_bi[10] = {0,0,0,0,1,1,1,2,2,3};
__constant__ int c_bj[10] = {0,1,2,3,1,2,3,2,3,3};

#define SWZ(o) ((o) ^ (((o) >> 3) & 0x70))

__device__ __forceinline__ uint32_t smem_u32(const void* p) {
    uint32_t a;
    asm("{ .reg .u64 t; cvta.to.shared.u64 t, %1; cvt.u32.u64 %0, t; }" : "=r"(a) : "l"(p));
    return a;
}

#define CP_ASYNC16(dst, src) \
    asm volatile("cp.async.ca.shared.global [%0], [%1], 16;" :: "r"(dst), "l"(src))
#define CP_COMMIT() asm volatile("cp.async.commit_group;" ::: "memory")
#define CP_WAIT0()  asm volatile("cp.async.wait_group 0;"  ::: "memory")

#define LDMX4(r0, r1, r2, r3, addr) \
    asm volatile("ldmatrix.sync.aligned.m8n8.x4.shared.b16 {%0,%1,%2,%3}, [%4];" \
                 : "=r"(r0), "=r"(r1), "=r"(r2), "=r"(r3) : "r"(addr))

#define MMAF16(d0, d1, d2, d3, a0, a1, a2, a3, b0, b1) \
    asm volatile("mma.sync.aligned.m16n8k16.row.col.f32.f16.f16.f32 " \
                 "{%0,%1,%2,%3}, {%4,%5,%6,%7}, {%8,%9}, {%0,%1,%2,%3};" \
                 : "+f"(d0), "+f"(d1), "+f"(d2), "+f"(d3) \
                 : "r"(a0), "r"(a1), "r"(a2), "r"(a3), "r"(b0), "r"(b1))

// SMEM: 2 stages x (A 16KB + B 16KB) = 64 KB pipeline.
// Epilogue reuses as float tile [128][132] = 67,584 B.
#define BUFSZ      16384
#define STAGE_SZ   (2 * BUFSZ)          // 32768
#define EPAD       132
#define SMEM_BYTES (BT * EPAD * 4)      // 67584

// ---------------- Phase 1: convert z -> fp16 ----------------
__global__ void convert_kernel(const float* __restrict__ z) {
    size_t i = ((size_t)blockIdx.x * blockDim.x + threadIdx.x) * 4;
    if (i >= (size_t)NTOT * D) return;
    float4 v = *reinterpret_cast<const float4*>(z + i);
    __half2 h0 = __floats2half2_rn(v.x, v.y);
    __half2 h1 = __floats2half2_rn(v.z, v.w);
    uint2 u = { *reinterpret_cast<uint32_t*>(&h0), *reinterpret_cast<uint32_t*>(&h1) };
    *reinterpret_cast<uint2*>(&g_zh[i]) = u;
}

// ---------------- Phase 2: fp16 HMMA GEMM + sigmoid ----------------
__global__ __launch_bounds__(256, 2)
void decoder_hmma_kernel(float* __restrict__ out) {
    extern __shared__ __align__(1024) char smem[];
    const uint32_t sbase = smem_u32(smem);
    float* smemF = reinterpret_cast<float*>(smem);

    const int tid = threadIdx.x;
    const int w   = tid >> 5;
    const int l   = tid & 31;
    const int wm  = w & 3;          // 0..3: 32-row block
    const int wn  = w >> 2;         // 0..1: 64-col block

    const int bx   = blockIdx.x;
    const int g    = bx / 10;
    const int pair = bx - g * 10;
    const int bi   = c_bi[pair];
    const int bj   = c_bj[pair];
    const bool diag = (bi == bj);

    const char* gA = reinterpret_cast<const char*>(g_zh) + ((size_t)g * NN + (size_t)bi * BT) * ROWB;
    const char* gB = reinterpret_cast<const char*>(g_zh) + ((size_t)g * NN + (size_t)bj * BT) * ROWB;

    // Chunk c: 64 fp16 = 128 bytes per row at byte offset c*128.
    auto prefetch = [&](int c, int stage) {
        const uint32_t dA = sbase + stage * STAGE_SZ;
        #pragma unroll
        for (int it = 0; it < 4; ++it) {
            int f   = it * 256 + tid;        // 0..1023
            int row = f >> 3;
            int q   = f & 7;
            const char* src = gA + (size_t)row * ROWB + c * 128 + q * 16;
            CP_ASYNC16(dA + SWZ((uint32_t)(row * 128 + q * 16)), src);
        }
        if (!diag) {
            const uint32_t dB = sbase + stage * STAGE_SZ + BUFSZ;
            #pragma unroll
            for (int it = 0; it < 4; ++it) {
                int f   = it * 256 + tid;
                int row = f >> 3;
                int q   = f & 7;
                const char* src = gB + (size_t)row * ROWB + c * 128 + q * 16;
                CP_ASYNC16(dB + SWZ((uint32_t)(row * 128 + q * 16)), src);
            }
        }
        CP_COMMIT();
    };

    float acc[2][8][4];
    #pragma unroll
    for (int mi = 0; mi < 2; ++mi)
        #pragma unroll
        for (int ni = 0; ni < 8; ++ni)
            #pragma unroll
            for (int r = 0; r < 4; ++r) acc[mi][ni][r] = 0.0f;

    // ldmatrix lane-derived constants
    const int mat = l >> 3;
    const int lr  = l & 7;
    const int a_roff = (mat & 1) * 8 + lr;
    const int a_koff = (mat >> 1) * 16;
    const int b_roff = (mat >> 1) * 8 + lr;
    const int b_koff = (mat & 1) * 16;

    prefetch(0, 0);

    for (int c = 0; c < NCH; ++c) {
        const int stage = c & 1;
        CP_WAIT0();
        __syncthreads();
        if (c + 1 < NCH) prefetch(c + 1, stage ^ 1);

        const uint32_t stA = sbase + stage * STAGE_SZ;
        const uint32_t stB = diag ? stA : (stA + BUFSZ);

        #pragma unroll
        for (int ks = 0; ks < 4; ++ks) {
            const int kb = ks * 32;
            uint32_t a[2][4];
            #pragma unroll
            for (int mi = 0; mi < 2; ++mi) {
                int row = wm * 32 + mi * 16 + a_roff;
                LDMX4(a[mi][0], a[mi][1], a[mi][2], a[mi][3],
                      stA + SWZ((uint32_t)(row * 128 + kb + a_koff)));
            }
            uint32_t b[8][2];
            #pragma unroll
            for (int np = 0; np < 4; ++np) {
                int row = wn * 64 + np * 16 + b_roff;
                LDMX4(b[np*2][0], b[np*2][1], b[np*2+1][0], b[np*2+1][1],
                      stB + SWZ((uint32_t)(row * 128 + kb + b_koff)));
            }
            #pragma unroll
            for (int mi = 0; mi < 2; ++mi)
                #pragma unroll
                for (int ni = 0; ni < 8; ++ni)
                    MMAF16(acc[mi][ni][0], acc[mi][ni][1], acc[mi][ni][2], acc[mi][ni][3],
                           a[mi][0], a[mi][1], a[mi][2], a[mi][3],
                           b[ni][0], b[ni][1]);
        }
        __syncthreads();
    }

    // ---- Epilogue: sigmoid -> smem tile -> coalesced stores (+ mirror) ----
    const int tq  = l >> 2;
    const int tc2 = (l & 3) * 2;
    #pragma unroll
    for (int mi = 0; mi < 2; ++mi) {
        #pragma unroll
        for (int ni = 0; ni < 8; ++ni) {
            int rr = wm * 32 + mi * 16 + tq;
            int cc = wn * 64 + ni * 8 + tc2;
            float2 v0, v1;
            v0.x = __fdividef(1.0f, 1.0f + __expf(-acc[mi][ni][0]));
            v0.y = __fdividef(1.0f, 1.0f + __expf(-acc[mi][ni][1]));
            v1.x = __fdividef(1.0f, 1.0f + __expf(-acc[mi][ni][2]));
            v1.y = __fdividef(1.0f, 1.0f + __expf(-acc[mi][ni][3]));
            *reinterpret_cast<float2*>(&smemF[rr * EPAD + cc])       = v0;
            *reinterpret_cast<float2*>(&smemF[(rr + 8) * EPAD + cc]) = v1;
        }
    }
    __syncthreads();

    float* outg = out + (size_t)g * NN * NN;
    const int rbase = bi * BT;
    const int cbase = bj * BT;

    #pragma unroll
    for (int t4 = tid; t4 < BT * 32; t4 += 256) {
        int row = t4 >> 5, q = t4 & 31;
        float4 v = *reinterpret_cast<const float4*>(&smemF[row * EPAD + q * 4]);
        *reinterpret_cast<float4*>(&outg[(size_t)(rbase + row) * NN + cbase + q * 4]) = v;
    }
    if (!diag) {
        #pragma unroll
        for (int t4 = tid; t4 < BT * 32; t4 += 256) {
            int tcc = t4 >> 5, q = t4 & 31;
            float4 v;
            v.x = smemF[(q * 4 + 0) * EPAD + tcc];
            v.y = smemF[(q * 4 + 1) * EPAD + tcc];
            v.z = smemF[(q * 4 + 2) * EPAD + tcc];
            v.w = smemF[(q * 4 + 3) * EPAD + tcc];
            *reinterpret_cast<float4*>(&outg[(size_t)(cbase + tcc) * NN + rbase + q * 4]) = v;
        }
    }
}

extern "C" void kernel_launch(void* const* d_in, const int* in_sizes, int n_in,
                              void* d_out, int out_size) {
    const float* z = (const float*)d_in[0];
    float* out = (float*)d_out;

    cudaFuncSetAttribute(decoder_hmma_kernel, cudaFuncAttributeMaxDynamicSharedMemorySize, SMEM_BYTES);

    size_t nvec = ((size_t)NTOT * D) / 4;
    convert_kernel<<<(int)((nvec + 255) / 256), 256>>>(z);
    decoder_hmma_kernel<<<G * 10, 256, SMEM_BYTES>>>(out);
}

// round 13
// speedup vs baseline: 1.8291x; 1.1156x over previous
#include <cuda_runtime.h>
#include <cuda_fp16.h>
#include <cstdint>

#define G     128
#define NN    512
#define D     256
#define ROWB  (D * 2)          // 512 bytes per fp16 row
#define KC    64               // K elems per chunk = 128 bytes
#define NCH   (D / KC)         // 4 chunks
#define NTOT  (G * NN)

// CTA tile: 128 rows x 256 cols. Warp tile: 64x64 (wm 0..1, wn 0..3).
#define TM    128
#define TN    256

// Scratch: z converted to fp16 (32 MB)
__device__ __half g_zh[(size_t)NTOT * D];

#define SWZ(o) ((o) ^ (((o) >> 3) & 0x70))

__device__ __forceinline__ uint32_t smem_u32(const void* p) {
    uint32_t a;
    asm("{ .reg .u64 t; cvta.to.shared.u64 t, %1; cvt.u32.u64 %0, t; }" : "=r"(a) : "l"(p));
    return a;
}

#define CP_ASYNC16(dst, src) \
    asm volatile("cp.async.ca.shared.global [%0], [%1], 16;" :: "r"(dst), "l"(src))
#define CP_COMMIT() asm volatile("cp.async.commit_group;" ::: "memory")
#define CP_WAIT0()  asm volatile("cp.async.wait_group 0;"  ::: "memory")

#define LDMX4(r0, r1, r2, r3, addr) \
    asm volatile("ldmatrix.sync.aligned.m8n8.x4.shared.b16 {%0,%1,%2,%3}, [%4];" \
                 : "=r"(r0), "=r"(r1), "=r"(r2), "=r"(r3) : "r"(addr))

#define MMAF16(d0, d1, d2, d3, a0, a1, a2, a3, b0, b1) \
    asm volatile("mma.sync.aligned.m16n8k16.row.col.f32.f16.f16.f32 " \
                 "{%0,%1,%2,%3}, {%4,%5,%6,%7}, {%8,%9}, {%0,%1,%2,%3};" \
                 : "+f"(d0), "+f"(d1), "+f"(d2), "+f"(d3) \
                 : "r"(a0), "r"(a1), "r"(a2), "r"(a3), "r"(b0), "r"(b1))

// SMEM: per stage A (128x128B = 16KB) + B (256x128B = 32KB) = 48KB; 2 stages = 96KB.
#define ABUF       16384
#define BBUF       32768
#define STAGE_SZ   (ABUF + BBUF)        // 49152
#define SMEM_BYTES (2 * STAGE_SZ)       // 98304

// ---------------- Phase 1: convert z -> fp16 (8 floats/thread) ----------------
__global__ void convert_kernel(const float* __restrict__ z) {
    size_t i = ((size_t)blockIdx.x * blockDim.x + threadIdx.x) * 8;
    if (i >= (size_t)NTOT * D) return;
    float4 v0 = *reinterpret_cast<const float4*>(z + i);
    float4 v1 = *reinterpret_cast<const float4*>(z + i + 4);
    __half2 h0 = __floats2half2_rn(v0.x, v0.y);
    __half2 h1 = __floats2half2_rn(v0.z, v0.w);
    __half2 h2 = __floats2half2_rn(v1.x, v1.y);
    __half2 h3 = __floats2half2_rn(v1.z, v1.w);
    uint4 u;
    u.x = *reinterpret_cast<uint32_t*>(&h0);
    u.y = *reinterpret_cast<uint32_t*>(&h1);
    u.z = *reinterpret_cast<uint32_t*>(&h2);
    u.w = *reinterpret_cast<uint32_t*>(&h3);
    *reinterpret_cast<uint4*>(&g_zh[i]) = u;
}

// ---------------- Phase 2: fp16 HMMA GEMM (full matrix) + sigmoid ----------------
__global__ __launch_bounds__(256, 1)
void decoder_hmma_kernel(float* __restrict__ out) {
    extern __shared__ __align__(1024) char smem[];
    const uint32_t sbase = smem_u32(smem);

    const int tid = threadIdx.x;
    const int w   = tid >> 5;
    const int l   = tid & 31;
    const int wm  = w & 1;          // 0..1: 64-row sub-block
    const int wn  = w >> 1;         // 0..3: 64-col sub-block

    const int bx  = blockIdx.x;
    const int g   = bx >> 3;
    const int ti  = bx & 7;
    const int tr  = ti >> 1;        // 0..3: 128-row tile
    const int tc  = ti & 1;         // 0..1: 256-col tile

    const char* gA = reinterpret_cast<const char*>(g_zh) + ((size_t)g * NN + (size_t)tr * TM) * ROWB;
    const char* gB = reinterpret_cast<const char*>(g_zh) + ((size_t)g * NN + (size_t)tc * TN) * ROWB;

    // Chunk c: 64 fp16 = 128B per row at byte offset c*128.
    auto prefetch = [&](int c, int stage) {
        const uint32_t dA = sbase + stage * STAGE_SZ;
        #pragma unroll
        for (int it = 0; it < 4; ++it) {
            int f   = it * 256 + tid;        // 0..1023 (128 rows x 8)
            int row = f >> 3;
            int q   = f & 7;
            const char* src = gA + (size_t)row * ROWB + c * 128 + q * 16;
            CP_ASYNC16(dA + SWZ((uint32_t)(row * 128 + q * 16)), src);
        }
        const uint32_t dB = sbase + stage * STAGE_SZ + ABUF;
        #pragma unroll
        for (int it = 0; it < 8; ++it) {
            int f   = it * 256 + tid;        // 0..2047 (256 rows x 8)
            int row = f >> 3;
            int q   = f & 7;
            const char* src = gB + (size_t)row * ROWB + c * 128 + q * 16;
            CP_ASYNC16(dB + SWZ((uint32_t)(row * 128 + q * 16)), src);
        }
        CP_COMMIT();
    };

    float acc[4][8][4];
    #pragma unroll
    for (int mi = 0; mi < 4; ++mi)
        #pragma unroll
        for (int ni = 0; ni < 8; ++ni)
            #pragma unroll
            for (int r = 0; r < 4; ++r) acc[mi][ni][r] = 0.0f;

    // ldmatrix lane-derived constants
    const int mat = l >> 3;
    const int lr  = l & 7;
    const int a_roff = (mat & 1) * 8 + lr;
    const int a_koff = (mat >> 1) * 16;
    const int b_roff = (mat >> 1) * 8 + lr;
    const int b_koff = (mat & 1) * 16;

    prefetch(0, 0);

    for (int c = 0; c < NCH; ++c) {
        const int stage = c & 1;
        CP_WAIT0();
        __syncthreads();
        if (c + 1 < NCH) prefetch(c + 1, stage ^ 1);

        const uint32_t stA = sbase + stage * STAGE_SZ;
        const uint32_t stB = stA + ABUF;

        #pragma unroll
        for (int ks = 0; ks < 4; ++ks) {
            const int kb = ks * 32;
            uint32_t a[4][4];
            #pragma unroll
            for (int mi = 0; mi < 4; ++mi) {
                int row = wm * 64 + mi * 16 + a_roff;
                LDMX4(a[mi][0], a[mi][1], a[mi][2], a[mi][3],
                      stA + SWZ((uint32_t)(row * 128 + kb + a_koff)));
            }
            uint32_t b[8][2];
            #pragma unroll
            for (int np = 0; np < 4; ++np) {
                int row = wn * 64 + np * 16 + b_roff;
                LDMX4(b[np*2][0], b[np*2][1], b[np*2+1][0], b[np*2+1][1],
                      stB + SWZ((uint32_t)(row * 128 + kb + b_koff)));
            }
            #pragma unroll
            for (int mi = 0; mi < 4; ++mi)
                #pragma unroll
                for (int ni = 0; ni < 8; ++ni)
                    MMAF16(acc[mi][ni][0], acc[mi][ni][1], acc[mi][ni][2], acc[mi][ni][3],
                           a[mi][0], a[mi][1], a[mi][2], a[mi][3],
                           b[ni][0], b[ni][1]);
        }
        __syncthreads();
    }

    // ---- Epilogue: sigmoid in regs -> direct float2 stores (32B row segments) ----
    float* outg = out + (size_t)g * NN * NN;
    const int tq  = l >> 2;          // 0..7
    const int tc2 = (l & 3) * 2;     // 0,2,4,6
    const int rbase = tr * TM + wm * 64;
    const int cbase = tc * TN + wn * 64;

    #pragma unroll
    for (int mi = 0; mi < 4; ++mi) {
        #pragma unroll
        for (int ni = 0; ni < 8; ++ni) {
            const int r0 = rbase + mi * 16 + tq;
            const int cc = cbase + ni * 8 + tc2;
            float2 v0, v1;
            v0.x = __fdividef(1.0f, 1.0f + __expf(-acc[mi][ni][0]));
            v0.y = __fdividef(1.0f, 1.0f + __expf(-acc[mi][ni][1]));
            v1.x = __fdividef(1.0f, 1.0f + __expf(-acc[mi][ni][2]));
            v1.y = __fdividef(1.0f, 1.0f + __expf(-acc[mi][ni][3]));
            *reinterpret_cast<float2*>(&outg[(size_t)r0 * NN + cc])       = v0;
            *reinterpret_cast<float2*>(&outg[(size_t)(r0 + 8) * NN + cc]) = v1;
        }
    }
}

extern "C" void kernel_launch(void* const* d_in, const int* in_sizes, int n_in,
                              void* d_out, int out_size) {
    const float* z = (const float*)d_in[0];
    float* out = (float*)d_out;

    cudaFuncSetAttribute(decoder_hmma_kernel, cudaFuncAttributeMaxDynamicSharedMemorySize, SMEM_BYTES);

    size_t nvec = ((size_t)NTOT * D) / 8;
    convert_kernel<<<(int)((nvec + 255) / 256), 256>>>(z);
    decoder_hmma_kernel<<<G * 8, 256, SMEM_BYTES>>>(out);
}